// round 2
// baseline (speedup 1.0000x reference)
#include <cuda_runtime.h>

#define B_   8
#define NQ_  64
#define N_   257
#define D_   768
#define H_   6
#define R_   64
#define DH_  128
#define MID_ 4096
#define BN_ROWS (B_*N_)    // 2056
#define BQ_ROWS (B_*NQ_)   // 512

// ---------------- scratch (device globals; no allocation allowed) ----------
__device__ float g_q[BQ_ROWS * (size_t)D_];
__device__ float g_k[BN_ROWS * (size_t)D_];
__device__ float g_mid[BN_ROWS * (size_t)MID_];
__device__ float g_w[(size_t)B_ * H_ * NQ_ * R_];
__device__ float g_outpre[BQ_ROWS * (size_t)D_];

// ---------------------------------------------------------------------------
// C[M,N] = A[M,K] @ B[N,K]^T   (row-major A and B; all our GEMMs are x @ W^T)
// 64x64 tile, BK=16, 256 threads, 4x4 microtile.
// ---------------------------------------------------------------------------
__global__ void gemm_nt_kernel(const float* __restrict__ A,
                               const float* __restrict__ Bm,
                               float* __restrict__ C,
                               int M, int N, int K) {
    __shared__ float As[16][64];
    __shared__ float Bs[16][64];
    const int tid = threadIdx.x;
    const int tx = tid & 15;
    const int ty = tid >> 4;
    const int rowBase = blockIdx.y * 64;
    const int colBase = blockIdx.x * 64;
    const int la = tid >> 2;         // 0..63
    const int lk = (tid & 3) << 2;   // 0,4,8,12

    float acc[4][4];
#pragma unroll
    for (int i = 0; i < 4; i++)
#pragma unroll
        for (int j = 0; j < 4; j++) acc[i][j] = 0.f;

    for (int k0 = 0; k0 < K; k0 += 16) {
        const int ar = rowBase + la;
        float4 a4 = make_float4(0.f, 0.f, 0.f, 0.f);
        if (ar < M) a4 = *(const float4*)(A + (size_t)ar * K + k0 + lk);
        As[lk + 0][la] = a4.x; As[lk + 1][la] = a4.y;
        As[lk + 2][la] = a4.z; As[lk + 3][la] = a4.w;

        const int br = colBase + la;
        float4 b4 = make_float4(0.f, 0.f, 0.f, 0.f);
        if (br < N) b4 = *(const float4*)(Bm + (size_t)br * K + k0 + lk);
        Bs[lk + 0][la] = b4.x; Bs[lk + 1][la] = b4.y;
        Bs[lk + 2][la] = b4.z; Bs[lk + 3][la] = b4.w;
        __syncthreads();

#pragma unroll
        for (int kk = 0; kk < 16; kk++) {
            const float4 av = *(const float4*)&As[kk][ty << 2];
            const float4 bv = *(const float4*)&Bs[kk][tx << 2];
            const float a0[4] = {av.x, av.y, av.z, av.w};
            const float b0[4] = {bv.x, bv.y, bv.z, bv.w};
#pragma unroll
            for (int i = 0; i < 4; i++)
#pragma unroll
                for (int j = 0; j < 4; j++) acc[i][j] += a0[i] * b0[j];
        }
        __syncthreads();
    }

#pragma unroll
    for (int i = 0; i < 4; i++) {
        const int r = rowBase + (ty << 2) + i;
        if (r >= M) break;
#pragma unroll
        for (int j = 0; j < 4; j++) {
            const int c = colBase + (tx << 2) + j;
            if (c < N) C[(size_t)r * N + c] = acc[i][j];
        }
    }
}

// ---------------------------------------------------------------------------
// Row LayerNorm over MID_=4096, in place. One block (256 thr) per row.
// ---------------------------------------------------------------------------
__global__ void ln_kernel(float* __restrict__ mid,
                          const float* __restrict__ g,
                          const float* __restrict__ bt) {
    const int row = blockIdx.x;
    float* p = mid + (size_t)row * MID_;
    const int tid = threadIdx.x;
    const int lane = tid & 31, warp = tid >> 5;

    float vals[16];
    float s = 0.f, ss = 0.f;
#pragma unroll
    for (int j = 0; j < 16; j++) {
        const float x = p[tid + (j << 8)];
        vals[j] = x; s += x; ss += x * x;
    }
#pragma unroll
    for (int off = 16; off; off >>= 1) {
        s  += __shfl_xor_sync(~0u, s,  off);
        ss += __shfl_xor_sync(~0u, ss, off);
    }
    __shared__ float rs[8], rss[8];
    if (lane == 0) { rs[warp] = s; rss[warp] = ss; }
    __syncthreads();
    s = 0.f; ss = 0.f;
#pragma unroll
    for (int k = 0; k < 8; k++) { s += rs[k]; ss += rss[k]; }
    const float mu  = s * (1.f / MID_);
    const float var = ss * (1.f / MID_) - mu * mu;
    const float inv = rsqrtf(var + 1e-5f);
#pragma unroll
    for (int j = 0; j < 16; j++) {
        const int idx = tid + (j << 8);
        p[idx] = (vals[j] - mu) * inv * g[idx] + bt[idx];
    }
}

// ---------------------------------------------------------------------------
// Attention + rank-space contraction.
// One block per (b, h, i). Computes attn over n=257 and
//   w[b,h,i,r] = sum_n attn[n] * mid[b,n, i*64 + r]
// ---------------------------------------------------------------------------
__global__ void attn_w_kernel(const float* __restrict__ qb,
                              const float* __restrict__ kb,
                              const float* __restrict__ mid,
                              float* __restrict__ w) {
    const int i = blockIdx.x;
    const int h = blockIdx.y;
    const int b = blockIdx.z;
    const int tid = threadIdx.x;          // 256
    const int lane = tid & 31, warp = tid >> 5;

    __shared__ float qs[DH_];
    __shared__ float sim[N_];
    __shared__ float red8[8];
    __shared__ float wred[4][R_];
    __shared__ float s_total;

    if (tid < DH_) qs[tid] = qb[((size_t)(b * NQ_ + i)) * D_ + h * DH_ + tid];
    __syncthreads();

    // sim[n] = (q . k_n) / sqrt(128). Warp per n, coalesced k reads.
    for (int n = warp; n < N_; n += 8) {
        const float* kp = kb + ((size_t)(b * N_ + n)) * D_ + h * DH_;
        float acc = 0.f;
#pragma unroll
        for (int d = lane; d < DH_; d += 32) acc += qs[d] * kp[d];
#pragma unroll
        for (int off = 16; off; off >>= 1) acc += __shfl_xor_sync(~0u, acc, off);
        if (lane == 0) sim[n] = acc * 0.0883883476483184406f;
    }
    __syncthreads();

    // softmax (unnormalized exp kept in sim, normalize via 1/total)
    float m = -1e30f;
    for (int n = tid; n < N_; n += 256) m = fmaxf(m, sim[n]);
#pragma unroll
    for (int off = 16; off; off >>= 1) m = fmaxf(m, __shfl_xor_sync(~0u, m, off));
    if (lane == 0) red8[warp] = m;
    __syncthreads();
    float mm = red8[0];
#pragma unroll
    for (int k = 1; k < 8; k++) mm = fmaxf(mm, red8[k]);
    __syncthreads();   // everyone read red8 before reuse

    float s = 0.f;
    for (int n = tid; n < N_; n += 256) {
        const float e = __expf(sim[n] - mm);
        sim[n] = e;
        s += e;
    }
#pragma unroll
    for (int off = 16; off; off >>= 1) s += __shfl_xor_sync(~0u, s, off);
    if (lane == 0) red8[warp] = s;
    __syncthreads();
    if (tid == 0) {
        float t = 0.f;
#pragma unroll
        for (int k = 0; k < 8; k++) t += red8[k];
        s_total = 1.f / t;
    }
    __syncthreads();

    // w[r] = sum_n sim[n] * mid[b,n, i*64+r]   (r = tid&63, 4 n-groups)
    const int r = tid & 63, grp = tid >> 6;
    float acc = 0.f;
    for (int n = grp; n < N_; n += 4)
        acc += sim[n] * mid[((size_t)(b * N_ + n)) * MID_ + i * R_ + r];
    wred[grp][r] = acc;
    __syncthreads();
    if (grp == 0) {
        const float v = (wred[0][r] + wred[1][r] + wred[2][r] + wred[3][r]) * s_total;
        w[(((size_t)b * H_ + h) * NQ_ + i) * R_ + r] = v;
    }
}

// ---------------------------------------------------------------------------
// Rank expansion: outpre[b,i,d] = sum_r Wconv[i,d,r] * w[b, d/128, i, r]
// One block per (b,i).
// ---------------------------------------------------------------------------
__global__ void convout_kernel(const float* __restrict__ w,
                               const float* __restrict__ Wconv,
                               float* __restrict__ outpre) {
    const int i = blockIdx.x % NQ_;
    const int b = blockIdx.x / NQ_;
    const int tid = threadIdx.x;   // 256

    __shared__ float ws[H_ * R_];  // 384 entries — MUST loop, blockDim is 256
    for (int j = tid; j < H_ * R_; j += 256)
        ws[j] = w[(((size_t)b * H_ + (j >> 6)) * NQ_ + i) * R_ + (j & 63)];
    __syncthreads();

    for (int d = tid; d < D_; d += 256) {
        const float* wc = Wconv + ((size_t)i * D_ + d) * R_;
        const float* wv = &ws[(d >> 7) * R_];
        float acc = 0.f;
#pragma unroll
        for (int r = 0; r < R_; r += 4) {
            const float4 c4 = *(const float4*)&wc[r];
            acc += c4.x * wv[r] + c4.y * wv[r + 1] + c4.z * wv[r + 2] + c4.w * wv[r + 3];
        }
        outpre[((size_t)b * NQ_ + i) * D_ + d] = acc;
    }
}

// ---------------------------------------------------------------------------
extern "C" void kernel_launch(void* const* d_in, const int* in_sizes, int n_in,
                              void* d_out, int out_size) {
    const float* x     = (const float*)d_in[0];
    const float* ctx   = (const float*)d_in[1];
    const float* Wq    = (const float*)d_in[2];
    const float* Wk    = (const float*)d_in[3];
    const float* Wv1   = (const float*)d_in[4];
    const float* ln_g  = (const float*)d_in[5];
    const float* ln_b  = (const float*)d_in[6];
    const float* Wconv = (const float*)d_in[7];
    const float* Wout  = (const float*)d_in[8];
    float* out = (float*)d_out;

    float *qp, *kp, *midp, *wp, *opp;
    cudaGetSymbolAddress((void**)&qp,   g_q);
    cudaGetSymbolAddress((void**)&kp,   g_k);
    cudaGetSymbolAddress((void**)&midp, g_mid);
    cudaGetSymbolAddress((void**)&wp,   g_w);
    cudaGetSymbolAddress((void**)&opp,  g_outpre);

    const dim3 blk(256);

    // q = x @ Wq^T          (512 x 768 x 768)
    gemm_nt_kernel<<<dim3(D_ / 64, (BQ_ROWS + 63) / 64), blk>>>(x, Wq, qp, BQ_ROWS, D_, D_);
    // k = ctx @ Wk^T        (2056 x 768 x 768)
    gemm_nt_kernel<<<dim3(D_ / 64, (BN_ROWS + 63) / 64), blk>>>(ctx, Wk, kp, BN_ROWS, D_, D_);
    // mid = ctx @ Wv1^T     (2056 x 4096 x 768)  -- dominant
    gemm_nt_kernel<<<dim3(MID_ / 64, (BN_ROWS + 63) / 64), blk>>>(ctx, Wv1, midp, BN_ROWS, MID_, D_);
    // LayerNorm rows of mid
    ln_kernel<<<BN_ROWS, 256>>>(midp, ln_g, ln_b);
    // attention + rank-space contraction -> w (b,h,q,r)
    attn_w_kernel<<<dim3(NQ_, H_, B_), 256>>>(qp, kp, midp, wp);
    // rank expansion through Wconv -> outpre (b,q,d)
    convout_kernel<<<BQ_ROWS, 256>>>(wp, Wconv, opp);
    // final = outpre @ Wout^T  (512 x 768 x 768)
    gemm_nt_kernel<<<dim3(D_ / 64, (BQ_ROWS + 63) / 64), blk>>>(opp, Wout, out, BQ_ROWS, D_, D_);
}

// round 3
// speedup vs baseline: 1.5066x; 1.5066x over previous
#include <cuda_runtime.h>
#include <cuda_bf16.h>
#include <cstdint>

#define B_   8
#define NQ_  64
#define N_   257
#define D_   768
#define H_   6
#define R_   64
#define DH_  128
#define MID_ 4096
#define BN_ROWS 2056
#define BQ_ROWS 512
#define K3  (3 * D_)          // 2304: split-bf16 K dimension

// ---------------- scratch (device globals; no allocation allowed) ----------
__device__ __nv_bfloat16 g_x2  [BQ_ROWS * (size_t)K3];
__device__ __nv_bfloat16 g_ctx2[BN_ROWS * (size_t)K3];
__device__ __nv_bfloat16 g_Wq2 [D_   * (size_t)K3];
__device__ __nv_bfloat16 g_Wk2 [D_   * (size_t)K3];
__device__ __nv_bfloat16 g_Wv12[MID_ * (size_t)K3];
__device__ __nv_bfloat16 g_Wout2[D_  * (size_t)K3];
__device__ __nv_bfloat16 g_op2 [BQ_ROWS * (size_t)K3];
__device__ float g_q[BQ_ROWS * (size_t)D_];
__device__ float g_k[BN_ROWS * (size_t)D_];
__device__ float g_mid[BN_ROWS * (size_t)MID_];
__device__ float g_w[(size_t)B_ * H_ * NQ_ * R_];
__device__ float g_outpre[BQ_ROWS * (size_t)D_];

// ---------------------------------------------------------------------------
// Split fp32 -> bf16 hi/lo, block-concatenated along K.
// MODE 0 (A-side): Y[m] = [hi | hi | lo]
// MODE 1 (B-side): Y[n] = [hi | lo | hi]
// => A2 @ B2^T = Ahi·Bhi + Ahi·Blo + Alo·Bhi  (drops lo·lo, ~2^-18)
// ---------------------------------------------------------------------------
template <int MODE>
__global__ void split_kernel(const float* __restrict__ X,
                             __nv_bfloat16* __restrict__ Y, int M) {
    const int i = blockIdx.x * 256 + threadIdx.x;
    if (i >= M * D_) return;
    const int row = i / D_, col = i - row * D_;
    const float x = X[i];
    const __nv_bfloat16 hi = __float2bfloat16(x);
    const __nv_bfloat16 lo = __float2bfloat16(x - __bfloat162float(hi));
    const size_t base = (size_t)row * K3 + col;
    if (MODE == 0) { Y[base] = hi; Y[base + D_] = hi; Y[base + 2 * D_] = lo; }
    else           { Y[base] = hi; Y[base + D_] = lo; Y[base + 2 * D_] = hi; }
}

// ---------------------------------------------------------------------------
// C[M,N] = A2[M,K3] @ B2[N,K3]^T  via mma.sync m16n8k16 bf16, fp32 accum.
// 128x128 block, BK=32, 256 threads = 8 warps (4M x 2N), warp tile 32x64.
// cp.async double buffer.
// ---------------------------------------------------------------------------
#define BM 128
#define BN 128
#define BKg 32
#define SA 40                 // padded smem stride (conflict-free frags)
#define NKIT (K3 / BKg)       // 72

__device__ __forceinline__ unsigned smem_u32(const void* p) {
    return (unsigned)__cvta_generic_to_shared(p);
}
#define CPA16(dst_u32, src_ptr) \
    asm volatile("cp.async.cg.shared.global [%0], [%1], 16;\n" :: "r"(dst_u32), "l"(src_ptr))

__global__ __launch_bounds__(256, 2)
void gemm_bf16_nt(const __nv_bfloat16* __restrict__ A,
                  const __nv_bfloat16* __restrict__ Bm,
                  float* __restrict__ C, int M, int N) {
    __shared__ __nv_bfloat16 As[2][BM][SA];
    __shared__ __nv_bfloat16 Bs[2][BN][SA];

    const int tid = threadIdx.x;
    const int warp = tid >> 5, lane = tid & 31;
    const int wm = warp & 3, wn = warp >> 2;      // 4 x 2 warp grid
    const int gr = lane >> 2, tig = lane & 3;     // mma fragment coords
    const int m0 = blockIdx.y * BM, n0 = blockIdx.x * BN;

    // loader: thread covers smem rows lr, lr+64 at col lc (8 bf16 = 16B)
    const int lr = tid >> 2;
    const int lc = (tid & 3) * 8;

    float acc[2][8][4];
#pragma unroll
    for (int mi = 0; mi < 2; mi++)
#pragma unroll
        for (int ni = 0; ni < 8; ni++)
#pragma unroll
            for (int j = 0; j < 4; j++) acc[mi][ni][j] = 0.f;

    auto issue_stage = [&](int kt, int buf) {
        const int k0 = kt * BKg;
        int ra = m0 + lr;      if (ra >= M) ra = M - 1;   // clamp: padding rows unused
        int rb = m0 + lr + 64; if (rb >= M) rb = M - 1;
        CPA16(smem_u32(&As[buf][lr][lc]),      A + (size_t)ra * K3 + k0 + lc);
        CPA16(smem_u32(&As[buf][lr + 64][lc]), A + (size_t)rb * K3 + k0 + lc);
        CPA16(smem_u32(&Bs[buf][lr][lc]),      Bm + (size_t)(n0 + lr) * K3 + k0 + lc);
        CPA16(smem_u32(&Bs[buf][lr + 64][lc]), Bm + (size_t)(n0 + lr + 64) * K3 + k0 + lc);
    };

    issue_stage(0, 0);
    asm volatile("cp.async.commit_group;\n" ::);

    for (int kt = 0; kt < NKIT; kt++) {
        const int buf = kt & 1;
        if (kt + 1 < NKIT) issue_stage(kt + 1, buf ^ 1);
        asm volatile("cp.async.commit_group;\n" ::);
        asm volatile("cp.async.wait_group 1;\n" ::);
        __syncthreads();

#pragma unroll
        for (int kk = 0; kk < 2; kk++) {
            const int kb = kk * 16;
            uint32_t a[2][4], b[8][2];
#pragma unroll
            for (int mi = 0; mi < 2; mi++) {
                const int r = wm * 32 + mi * 16 + gr;
                a[mi][0] = *(const uint32_t*)&As[buf][r    ][kb + 2 * tig];
                a[mi][1] = *(const uint32_t*)&As[buf][r + 8][kb + 2 * tig];
                a[mi][2] = *(const uint32_t*)&As[buf][r    ][kb + 2 * tig + 8];
                a[mi][3] = *(const uint32_t*)&As[buf][r + 8][kb + 2 * tig + 8];
            }
#pragma unroll
            for (int ni = 0; ni < 8; ni++) {
                const int c = wn * 64 + ni * 8 + gr;
                b[ni][0] = *(const uint32_t*)&Bs[buf][c][kb + 2 * tig];
                b[ni][1] = *(const uint32_t*)&Bs[buf][c][kb + 2 * tig + 8];
            }
#pragma unroll
            for (int mi = 0; mi < 2; mi++)
#pragma unroll
                for (int ni = 0; ni < 8; ni++)
                    asm volatile(
                        "mma.sync.aligned.m16n8k16.row.col.f32.bf16.bf16.f32 "
                        "{%0,%1,%2,%3}, {%4,%5,%6,%7}, {%8,%9}, {%0,%1,%2,%3};\n"
                        : "+f"(acc[mi][ni][0]), "+f"(acc[mi][ni][1]),
                          "+f"(acc[mi][ni][2]), "+f"(acc[mi][ni][3])
                        : "r"(a[mi][0]), "r"(a[mi][1]), "r"(a[mi][2]), "r"(a[mi][3]),
                          "r"(b[ni][0]), "r"(b[ni][1]));
        }
        __syncthreads();   // before next issue overwrites buf^1
    }

#pragma unroll
    for (int mi = 0; mi < 2; mi++)
#pragma unroll
        for (int ni = 0; ni < 8; ni++) {
            const int c = n0 + wn * 64 + ni * 8 + 2 * tig;
            int r = m0 + wm * 32 + mi * 16 + gr;
            if (r < M) *(float2*)&C[(size_t)r * N + c] =
                make_float2(acc[mi][ni][0], acc[mi][ni][1]);
            r += 8;
            if (r < M) *(float2*)&C[(size_t)r * N + c] =
                make_float2(acc[mi][ni][2], acc[mi][ni][3]);
        }
}

// ---------------------------------------------------------------------------
// Row LayerNorm over MID_=4096, in place. One block (256 thr) per row.
// ---------------------------------------------------------------------------
__global__ void ln_kernel(float* __restrict__ mid,
                          const float* __restrict__ g,
                          const float* __restrict__ bt) {
    const int row = blockIdx.x;
    float* p = mid + (size_t)row * MID_;
    const int tid = threadIdx.x;
    const int lane = tid & 31, warp = tid >> 5;

    float vals[16];
    float s = 0.f, ss = 0.f;
#pragma unroll
    for (int j = 0; j < 16; j++) {
        const float x = p[tid + (j << 8)];
        vals[j] = x; s += x; ss += x * x;
    }
#pragma unroll
    for (int off = 16; off; off >>= 1) {
        s  += __shfl_xor_sync(~0u, s,  off);
        ss += __shfl_xor_sync(~0u, ss, off);
    }
    __shared__ float rs[8], rss[8];
    if (lane == 0) { rs[warp] = s; rss[warp] = ss; }
    __syncthreads();
    s = 0.f; ss = 0.f;
#pragma unroll
    for (int k = 0; k < 8; k++) { s += rs[k]; ss += rss[k]; }
    const float mu  = s * (1.f / MID_);
    const float var = ss * (1.f / MID_) - mu * mu;
    const float inv = rsqrtf(var + 1e-5f);
#pragma unroll
    for (int j = 0; j < 16; j++) {
        const int idx = tid + (j << 8);
        p[idx] = (vals[j] - mu) * inv * g[idx] + bt[idx];
    }
}

// ---------------------------------------------------------------------------
// Attention + rank-space contraction (unchanged, fp32-exact).
// ---------------------------------------------------------------------------
__global__ void attn_w_kernel(const float* __restrict__ qb,
                              const float* __restrict__ kb,
                              const float* __restrict__ mid,
                              float* __restrict__ w) {
    const int i = blockIdx.x;
    const int h = blockIdx.y;
    const int b = blockIdx.z;
    const int tid = threadIdx.x;
    const int lane = tid & 31, warp = tid >> 5;

    __shared__ float qs[DH_];
    __shared__ float sim[N_];
    __shared__ float red8[8];
    __shared__ float wred[4][R_];
    __shared__ float s_total;

    if (tid < DH_) qs[tid] = qb[((size_t)(b * NQ_ + i)) * D_ + h * DH_ + tid];
    __syncthreads();

    for (int n = warp; n < N_; n += 8) {
        const float* kp = kb + ((size_t)(b * N_ + n)) * D_ + h * DH_;
        float acc = 0.f;
#pragma unroll
        for (int d = lane; d < DH_; d += 32) acc += qs[d] * kp[d];
#pragma unroll
        for (int off = 16; off; off >>= 1) acc += __shfl_xor_sync(~0u, acc, off);
        if (lane == 0) sim[n] = acc * 0.0883883476483184406f;
    }
    __syncthreads();

    float m = -1e30f;
    for (int n = tid; n < N_; n += 256) m = fmaxf(m, sim[n]);
#pragma unroll
    for (int off = 16; off; off >>= 1) m = fmaxf(m, __shfl_xor_sync(~0u, m, off));
    if (lane == 0) red8[warp] = m;
    __syncthreads();
    float mm = red8[0];
#pragma unroll
    for (int k = 1; k < 8; k++) mm = fmaxf(mm, red8[k]);
    __syncthreads();

    float s = 0.f;
    for (int n = tid; n < N_; n += 256) {
        const float e = __expf(sim[n] - mm);
        sim[n] = e;
        s += e;
    }
#pragma unroll
    for (int off = 16; off; off >>= 1) s += __shfl_xor_sync(~0u, s, off);
    if (lane == 0) red8[warp] = s;
    __syncthreads();
    if (tid == 0) {
        float t = 0.f;
#pragma unroll
        for (int k = 0; k < 8; k++) t += red8[k];
        s_total = 1.f / t;
    }
    __syncthreads();

    const int r = tid & 63, grp = tid >> 6;
    float acc = 0.f;
    for (int n = grp; n < N_; n += 4)
        acc += sim[n] * mid[((size_t)(b * N_ + n)) * MID_ + i * R_ + r];
    wred[grp][r] = acc;
    __syncthreads();
    if (grp == 0) {
        const float v = (wred[0][r] + wred[1][r] + wred[2][r] + wred[3][r]) * s_total;
        w[(((size_t)b * H_ + h) * NQ_ + i) * R_ + r] = v;
    }
}

// ---------------------------------------------------------------------------
// Rank expansion: outpre[b,i,d] = sum_r Wconv[i,d,r] * w[b, d/128, i, r]
// ---------------------------------------------------------------------------
__global__ void convout_kernel(const float* __restrict__ w,
                               const float* __restrict__ Wconv,
                               float* __restrict__ outpre) {
    const int i = blockIdx.x % NQ_;
    const int b = blockIdx.x / NQ_;
    const int tid = threadIdx.x;

    __shared__ float ws[H_ * R_];
    for (int j = tid; j < H_ * R_; j += 256)
        ws[j] = w[(((size_t)b * H_ + (j >> 6)) * NQ_ + i) * R_ + (j & 63)];
    __syncthreads();

    for (int d = tid; d < D_; d += 256) {
        const float* wc = Wconv + ((size_t)i * D_ + d) * R_;
        const float* wv = &ws[(d >> 7) * R_];
        float acc = 0.f;
#pragma unroll
        for (int r = 0; r < R_; r += 4) {
            const float4 c4 = *(const float4*)&wc[r];
            acc += c4.x * wv[r] + c4.y * wv[r + 1] + c4.z * wv[r + 2] + c4.w * wv[r + 3];
        }
        outpre[((size_t)b * NQ_ + i) * D_ + d] = acc;
    }
}

// ---------------------------------------------------------------------------
extern "C" void kernel_launch(void* const* d_in, const int* in_sizes, int n_in,
                              void* d_out, int out_size) {
    const float* x     = (const float*)d_in[0];
    const float* ctx   = (const float*)d_in[1];
    const float* Wq    = (const float*)d_in[2];
    const float* Wk    = (const float*)d_in[3];
    const float* Wv1   = (const float*)d_in[4];
    const float* ln_g  = (const float*)d_in[5];
    const float* ln_b  = (const float*)d_in[6];
    const float* Wconv = (const float*)d_in[7];
    const float* Wout  = (const float*)d_in[8];
    float* out = (float*)d_out;

    __nv_bfloat16 *x2, *ctx2, *Wq2, *Wk2, *Wv12, *Wout2, *op2;
    float *qp, *kp, *midp, *wp, *opp;
    cudaGetSymbolAddress((void**)&x2,   g_x2);
    cudaGetSymbolAddress((void**)&ctx2, g_ctx2);
    cudaGetSymbolAddress((void**)&Wq2,  g_Wq2);
    cudaGetSymbolAddress((void**)&Wk2,  g_Wk2);
    cudaGetSymbolAddress((void**)&Wv12, g_Wv12);
    cudaGetSymbolAddress((void**)&Wout2,g_Wout2);
    cudaGetSymbolAddress((void**)&op2,  g_op2);
    cudaGetSymbolAddress((void**)&qp,   g_q);
    cudaGetSymbolAddress((void**)&kp,   g_k);
    cudaGetSymbolAddress((void**)&midp, g_mid);
    cudaGetSymbolAddress((void**)&wp,   g_w);
    cudaGetSymbolAddress((void**)&opp,  g_outpre);

    const int T = 256;
    auto blks = [](int n) { return (n + 255) / 256; };

    // split conversions (A-side: activations, B-side: weights)
    split_kernel<0><<<blks(BQ_ROWS * D_), T>>>(x,    x2,   BQ_ROWS);
    split_kernel<0><<<blks(BN_ROWS * D_), T>>>(ctx,  ctx2, BN_ROWS);
    split_kernel<1><<<blks(D_ * D_),      T>>>(Wq,   Wq2,  D_);
    split_kernel<1><<<blks(D_ * D_),      T>>>(Wk,   Wk2,  D_);
    split_kernel<1><<<blks(MID_ * D_),    T>>>(Wv1,  Wv12, MID_);
    split_kernel<1><<<blks(D_ * D_),      T>>>(Wout, Wout2, D_);

    // q = x @ Wq^T
    gemm_bf16_nt<<<dim3(D_ / BN, (BQ_ROWS + BM - 1) / BM), T>>>(x2, Wq2, qp, BQ_ROWS, D_);
    // k = ctx @ Wk^T
    gemm_bf16_nt<<<dim3(D_ / BN, (BN_ROWS + BM - 1) / BM), T>>>(ctx2, Wk2, kp, BN_ROWS, D_);
    // mid = ctx @ Wv1^T  (dominant)
    gemm_bf16_nt<<<dim3(MID_ / BN, (BN_ROWS + BM - 1) / BM), T>>>(ctx2, Wv12, midp, BN_ROWS, MID_);

    ln_kernel<<<BN_ROWS, 256>>>(midp, ln_g, ln_b);
    attn_w_kernel<<<dim3(NQ_, H_, B_), 256>>>(qp, kp, midp, wp);
    convout_kernel<<<BQ_ROWS, 256>>>(wp, Wconv, opp);

    // final = outpre @ Wout^T
    split_kernel<0><<<blks(BQ_ROWS * D_), T>>>(opp, op2, BQ_ROWS);
    gemm_bf16_nt<<<dim3(D_ / BN, (BQ_ROWS + BM - 1) / BM), T>>>(op2, Wout2, out, BQ_ROWS, D_);
}

// round 5
// speedup vs baseline: 2.0425x; 1.3557x over previous
#include <cuda_runtime.h>
#include <cuda_bf16.h>
#include <cstdint>

#define B_   8
#define NQ_  64
#define N_   257
#define D_   768
#define H_   6
#define R_   64
#define DH_  128
#define MID_ 4096
#define BN_ROWS 2056
#define BQ_ROWS 512
#define K3  (3 * D_)          // 2304: split-bf16 K dimension
#define NKT (K3 / 64)         // 36 k-tiles of 64

// ---------------- scratch (device globals; no allocation allowed) ----------
__device__ __align__(256) __nv_bfloat16 g_x2  [BQ_ROWS * (size_t)K3];
__device__ __align__(256) __nv_bfloat16 g_ctx2[BN_ROWS * (size_t)K3];
__device__ __align__(256) __nv_bfloat16 g_Wq2 [D_   * (size_t)K3];
__device__ __align__(256) __nv_bfloat16 g_Wk2 [D_   * (size_t)K3];
__device__ __align__(256) __nv_bfloat16 g_Wv12[MID_ * (size_t)K3];
__device__ __align__(256) __nv_bfloat16 g_Wout2[D_  * (size_t)K3];
__device__ __align__(256) __nv_bfloat16 g_op2 [BQ_ROWS * (size_t)K3];
__device__ float g_q[BQ_ROWS * (size_t)D_];
__device__ float g_k[BN_ROWS * (size_t)D_];
__device__ float g_mid[BN_ROWS * (size_t)MID_];
__device__ float g_w[(size_t)B_ * H_ * NQ_ * R_];
__device__ float g_outpre[BQ_ROWS * (size_t)D_];

// ---------------------------- PTX helpers ----------------------------------
__device__ __forceinline__ unsigned smem_u32(const void* p) {
    return (unsigned)__cvta_generic_to_shared(p);
}
#define CPA16(dst_u32, src_ptr) \
    asm volatile("cp.async.cg.shared.global [%0], [%1], 16;\n" :: "r"(dst_u32), "l"(src_ptr))
#define LDSM_X4(r0, r1, r2, r3, addr) \
    asm volatile("ldmatrix.sync.aligned.m8n8.x4.shared.b16 {%0,%1,%2,%3}, [%4];" \
                 : "=r"(r0), "=r"(r1), "=r"(r2), "=r"(r3) : "r"(addr))

__device__ __forceinline__ uint32_t sw128(uint32_t off) {
    return off ^ ((off >> 3) & 0x70);
}

// ---------------------------------------------------------------------------
// Split fp32 -> bf16 hi/lo, block-concatenated along K.
// MODE 0 (A-side): [hi | hi | lo]   MODE 1 (B-side): [hi | lo | hi]
// => A2 @ B2^T = Ahi·Bhi + Ahi·Blo + Alo·Bhi  (drops lo·lo, ~2^-18)
// ---------------------------------------------------------------------------
template <int MODE>
__global__ void split_kernel(const float* __restrict__ X,
                             __nv_bfloat16* __restrict__ Y, int M) {
    const int i = blockIdx.x * 256 + threadIdx.x;
    if (i >= M * D_) return;
    const int row = i / D_, col = i - row * D_;
    const float x = X[i];
    const __nv_bfloat16 hi = __float2bfloat16(x);
    const __nv_bfloat16 lo = __float2bfloat16(x - __bfloat162float(hi));
    const size_t base = (size_t)row * K3 + col;
    if (MODE == 0) { Y[base] = hi; Y[base + D_] = hi; Y[base + 2 * D_] = lo; }
    else           { Y[base] = hi; Y[base + D_] = lo; Y[base + 2 * D_] = hi; }
}

// ---------------------------------------------------------------------------
// C[M,N] = A[M,K3] @ B[N,K3]^T via mma.sync m16n8k16 bf16 + ldmatrix.
// 128x128 block tile, BK=64, 3-stage cp.async pipeline, 256 thr = 8 warps
// (4M x 2N), warp tile 32x64. SW128-swizzled smem (128B rows of 64 bf16).
// ---------------------------------------------------------------------------
#define STG_BYTES 32768            // (128 + 128) rows * 128 B

__global__ __launch_bounds__(256, 2)
void gemm_mma(const __nv_bfloat16* __restrict__ A,
              const __nv_bfloat16* __restrict__ Bm,
              float* __restrict__ C, int M, int Ncols) {
    extern __shared__ char dyn[];
    const uint32_t base = smem_u32(dyn);

    const int tid = threadIdx.x;
    const int warp = tid >> 5, lane = tid & 31;
    const int wm = warp & 3, wn = warp >> 2;          // 4 x 2 warps
    const int gr = lane >> 2, tig = lane & 3;         // mma frag coords
    const int m0 = blockIdx.y * 128, n0 = blockIdx.x * 128;

    // per-lane ldmatrix row/col mapping (see mma fragment layouts)
    const int a_r = (lane & 7) + ((lane >> 3) & 1) * 8;   // + row0
    const int a_k = (lane >> 4) * 8;                      // + k16
    const int b_c = (lane & 7) + ((lane >> 4) & 1) * 8;   // + col0
    const int b_k = ((lane >> 3) & 1) * 8;                // + k16

    float acc[2][8][4];
#pragma unroll
    for (int mi = 0; mi < 2; mi++)
#pragma unroll
        for (int ni = 0; ni < 8; ni++)
#pragma unroll
            for (int j = 0; j < 4; j++) acc[mi][ni][j] = 0.f;

    auto load_stage = [&](int kt) {
        const uint32_t sb = base + (kt % 3) * STG_BYTES;
        const int k0 = kt * 64;
#pragma unroll
        for (int i = 0; i < 4; i++) {                 // A: 128 rows x 128B
            const int c = tid + i * 256;
            const int row = c >> 3, c16 = c & 7;
            int grow = m0 + row; if (grow >= M) grow = M - 1;
            CPA16(sb + sw128((uint32_t)(row * 128 + c16 * 16)),
                  A + (size_t)grow * K3 + k0 + c16 * 8);
        }
#pragma unroll
        for (int i = 0; i < 4; i++) {                 // B: 128 rows x 128B
            const int c = tid + i * 256;
            const int row = c >> 3, c16 = c & 7;
            CPA16(sb + 16384 + sw128((uint32_t)(row * 128 + c16 * 16)),
                  Bm + (size_t)(n0 + row) * K3 + k0 + c16 * 8);
        }
        asm volatile("cp.async.commit_group;\n" ::);
    };

    load_stage(0);
    load_stage(1);

    for (int kt = 0; kt < NKT; kt++) {
        const int s = kt % 3;
        asm volatile("cp.async.wait_group 1;\n" ::);   // stage kt arrived
        __syncthreads();                               // all done with kt-1
        if (kt + 2 < NKT) load_stage(kt + 2);
        else asm volatile("cp.async.commit_group;\n" ::);  // keep counts

        const uint32_t sA = base + s * STG_BYTES;
        const uint32_t sB = sA + 16384;
#pragma unroll
        for (int kk = 0; kk < 4; kk++) {
            const int k16 = kk * 16;
            uint32_t a[2][4], b[4][4];
#pragma unroll
            for (int mi = 0; mi < 2; mi++) {
                const int r = wm * 32 + mi * 16 + a_r;
                LDSM_X4(a[mi][0], a[mi][1], a[mi][2], a[mi][3],
                        sA + sw128((uint32_t)(r * 128 + (k16 + a_k) * 2)));
            }
#pragma unroll
            for (int nj = 0; nj < 4; nj++) {
                const int cth = wn * 64 + nj * 16 + b_c;
                LDSM_X4(b[nj][0], b[nj][1], b[nj][2], b[nj][3],
                        sB + sw128((uint32_t)(cth * 128 + (k16 + b_k) * 2)));
            }
#pragma unroll
            for (int mi = 0; mi < 2; mi++)
#pragma unroll
                for (int ni = 0; ni < 8; ni++) {
                    const uint32_t b0 = b[ni >> 1][(ni & 1) * 2];
                    const uint32_t b1 = b[ni >> 1][(ni & 1) * 2 + 1];
                    asm volatile(
                        "mma.sync.aligned.m16n8k16.row.col.f32.bf16.bf16.f32 "
                        "{%0,%1,%2,%3}, {%4,%5,%6,%7}, {%8,%9}, {%0,%1,%2,%3};\n"
                        : "+f"(acc[mi][ni][0]), "+f"(acc[mi][ni][1]),
                          "+f"(acc[mi][ni][2]), "+f"(acc[mi][ni][3])
                        : "r"(a[mi][0]), "r"(a[mi][1]), "r"(a[mi][2]), "r"(a[mi][3]),
                          "r"(b0), "r"(b1));
                }
        }
    }

#pragma unroll
    for (int mi = 0; mi < 2; mi++)
#pragma unroll
        for (int ni = 0; ni < 8; ni++) {
            const int c = n0 + wn * 64 + ni * 8 + 2 * tig;
            int r = m0 + wm * 32 + mi * 16 + gr;
            if (r < M) *(float2*)&C[(size_t)r * Ncols + c] =
                make_float2(acc[mi][ni][0], acc[mi][ni][1]);
            r += 8;
            if (r < M) *(float2*)&C[(size_t)r * Ncols + c] =
                make_float2(acc[mi][ni][2], acc[mi][ni][3]);
        }
}

// ---------------------------------------------------------------------------
// Row LayerNorm over MID_=4096, in place. One block (256 thr) per row.
// ---------------------------------------------------------------------------
__global__ void ln_kernel(float* __restrict__ mid,
                          const float* __restrict__ g,
                          const float* __restrict__ bt) {
    const int row = blockIdx.x;
    float* p = mid + (size_t)row * MID_;
    const int tid = threadIdx.x;
    const int lane = tid & 31, warp = tid >> 5;

    float vals[16];
    float s = 0.f, ss = 0.f;
#pragma unroll
    for (int j = 0; j < 16; j++) {
        const float x = p[tid + (j << 8)];
        vals[j] = x; s += x; ss += x * x;
    }
#pragma unroll
    for (int off = 16; off; off >>= 1) {
        s  += __shfl_xor_sync(~0u, s,  off);
        ss += __shfl_xor_sync(~0u, ss, off);
    }
    __shared__ float rs[8], rss[8];
    if (lane == 0) { rs[warp] = s; rss[warp] = ss; }
    __syncthreads();
    s = 0.f; ss = 0.f;
#pragma unroll
    for (int k = 0; k < 8; k++) { s += rs[k]; ss += rss[k]; }
    const float mu  = s * (1.f / MID_);
    const float var = ss * (1.f / MID_) - mu * mu;
    const float inv = rsqrtf(var + 1e-5f);
#pragma unroll
    for (int j = 0; j < 16; j++) {
        const int idx = tid + (j << 8);
        p[idx] = (vals[j] - mu) * inv * g[idx] + bt[idx];
    }
}

// ---------------------------------------------------------------------------
// Attention + rank-space contraction (fp32-exact).
// ---------------------------------------------------------------------------
__global__ void attn_w_kernel(const float* __restrict__ qb,
                              const float* __restrict__ kb,
                              const float* __restrict__ mid,
                              float* __restrict__ w) {
    const int i = blockIdx.x;
    const int h = blockIdx.y;
    const int b = blockIdx.z;
    const int tid = threadIdx.x;
    const int lane = tid & 31, warp = tid >> 5;

    __shared__ float qs[DH_];
    __shared__ float sim[N_];
    __shared__ float red8[8];
    __shared__ float wred[4][R_];
    __shared__ float s_total;

    if (tid < DH_) qs[tid] = qb[((size_t)(b * NQ_ + i)) * D_ + h * DH_ + tid];
    __syncthreads();

    for (int n = warp; n < N_; n += 8) {
        const float* kp = kb + ((size_t)(b * N_ + n)) * D_ + h * DH_;
        float acc = 0.f;
#pragma unroll
        for (int d = lane; d < DH_; d += 32) acc += qs[d] * kp[d];
#pragma unroll
        for (int off = 16; off; off >>= 1) acc += __shfl_xor_sync(~0u, acc, off);
        if (lane == 0) sim[n] = acc * 0.0883883476483184406f;
    }
    __syncthreads();

    float m = -1e30f;
    for (int n = tid; n < N_; n += 256) m = fmaxf(m, sim[n]);
#pragma unroll
    for (int off = 16; off; off >>= 1) m = fmaxf(m, __shfl_xor_sync(~0u, m, off));
    if (lane == 0) red8[warp] = m;
    __syncthreads();
    float mm = red8[0];
#pragma unroll
    for (int k = 1; k < 8; k++) mm = fmaxf(mm, red8[k]);
    __syncthreads();

    float s = 0.f;
    for (int n = tid; n < N_; n += 256) {
        const float e = __expf(sim[n] - mm);
        sim[n] = e;
        s += e;
    }
#pragma unroll
    for (int off = 16; off; off >>= 1) s += __shfl_xor_sync(~0u, s, off);
    if (lane == 0) red8[warp] = s;
    __syncthreads();
    if (tid == 0) {
        float t = 0.f;
#pragma unroll
        for (int k = 0; k < 8; k++) t += red8[k];
        s_total = 1.f / t;
    }
    __syncthreads();

    const int r = tid & 63, grp = tid >> 6;
    float acc = 0.f;
    for (int n = grp; n < N_; n += 4)
        acc += sim[n] * mid[((size_t)(b * N_ + n)) * MID_ + i * R_ + r];
    wred[grp][r] = acc;
    __syncthreads();
    if (grp == 0) {
        const float v = (wred[0][r] + wred[1][r] + wred[2][r] + wred[3][r]) * s_total;
        w[(((size_t)b * H_ + h) * NQ_ + i) * R_ + r] = v;
    }
}

// ---------------------------------------------------------------------------
// Rank expansion: outpre[b,i,d] = sum_r Wconv[i,d,r] * w[b, d/128, i, r]
// ---------------------------------------------------------------------------
__global__ void convout_kernel(const float* __restrict__ w,
                               const float* __restrict__ Wconv,
                               float* __restrict__ outpre) {
    const int i = blockIdx.x % NQ_;
    const int b = blockIdx.x / NQ_;
    const int tid = threadIdx.x;

    __shared__ float ws[H_ * R_];
    for (int j = tid; j < H_ * R_; j += 256)
        ws[j] = w[(((size_t)b * H_ + (j >> 6)) * NQ_ + i) * R_ + (j & 63)];
    __syncthreads();

    for (int d = tid; d < D_; d += 256) {
        const float* wc = Wconv + ((size_t)i * D_ + d) * R_;
        const float* wv = &ws[(d >> 7) * R_];
        float acc = 0.f;
#pragma unroll
        for (int r = 0; r < R_; r += 4) {
            const float4 c4 = *(const float4*)&wc[r];
            acc += c4.x * wv[r] + c4.y * wv[r + 1] + c4.z * wv[r + 2] + c4.w * wv[r + 3];
        }
        outpre[((size_t)b * NQ_ + i) * D_ + d] = acc;
    }
}

// ---------------------------------------------------------------------------
extern "C" void kernel_launch(void* const* d_in, const int* in_sizes, int n_in,
                              void* d_out, int out_size) {
    const float* x     = (const float*)d_in[0];
    const float* ctx   = (const float*)d_in[1];
    const float* Wq    = (const float*)d_in[2];
    const float* Wk    = (const float*)d_in[3];
    const float* Wv1   = (const float*)d_in[4];
    const float* ln_g  = (const float*)d_in[5];
    const float* ln_b  = (const float*)d_in[6];
    const float* Wconv = (const float*)d_in[7];
    const float* Wout  = (const float*)d_in[8];
    float* out = (float*)d_out;

    __nv_bfloat16 *x2, *ctx2, *Wq2, *Wk2, *Wv12, *Wout2, *op2;
    float *qp, *kp, *midp, *wp, *opp;
    cudaGetSymbolAddress((void**)&x2,   g_x2);
    cudaGetSymbolAddress((void**)&ctx2, g_ctx2);
    cudaGetSymbolAddress((void**)&Wq2,  g_Wq2);
    cudaGetSymbolAddress((void**)&Wk2,  g_Wk2);
    cudaGetSymbolAddress((void**)&Wv12, g_Wv12);
    cudaGetSymbolAddress((void**)&Wout2,g_Wout2);
    cudaGetSymbolAddress((void**)&op2,  g_op2);
    cudaGetSymbolAddress((void**)&qp,   g_q);
    cudaGetSymbolAddress((void**)&kp,   g_k);
    cudaGetSymbolAddress((void**)&midp, g_mid);
    cudaGetSymbolAddress((void**)&wp,   g_w);
    cudaGetSymbolAddress((void**)&opp,  g_outpre);

    const int SMEM = 3 * STG_BYTES;   // 98304
    cudaFuncSetAttribute(gemm_mma, cudaFuncAttributeMaxDynamicSharedMemorySize, SMEM);

    const int T = 256;
    auto blks = [](int n) { return (n + 255) / 256; };

    // split conversions (A-side: activations, B-side: weights)
    split_kernel<0><<<blks(BQ_ROWS * D_), T>>>(x,    x2,   BQ_ROWS);
    split_kernel<0><<<blks(BN_ROWS * D_), T>>>(ctx,  ctx2, BN_ROWS);
    split_kernel<1><<<blks(D_ * D_),      T>>>(Wq,   Wq2,  D_);
    split_kernel<1><<<blks(D_ * D_),      T>>>(Wk,   Wk2,  D_);
    split_kernel<1><<<blks(MID_ * D_),    T>>>(Wv1,  Wv12, MID_);
    split_kernel<1><<<blks(D_ * D_),      T>>>(Wout, Wout2, D_);

    // q = x @ Wq^T          (512 x 768)
    gemm_mma<<<dim3(D_ / 128, BQ_ROWS / 128), T, SMEM>>>(x2, Wq2, qp, BQ_ROWS, D_);
    // k = ctx @ Wk^T        (2056 x 768)
    gemm_mma<<<dim3(D_ / 128, (BN_ROWS + 127) / 128), T, SMEM>>>(ctx2, Wk2, kp, BN_ROWS, D_);
    // mid = ctx @ Wv1^T     (2056 x 4096)  -- dominant
    gemm_mma<<<dim3(MID_ / 128, (BN_ROWS + 127) / 128), T, SMEM>>>(ctx2, Wv12, midp, BN_ROWS, MID_);

    ln_kernel<<<BN_ROWS, 256>>>(midp, ln_g, ln_b);
    attn_w_kernel<<<dim3(NQ_, H_, B_), 256>>>(qp, kp, midp, wp);
    convout_kernel<<<BQ_ROWS, 256>>>(wp, Wconv, opp);

    // final = outpre @ Wout^T  (512 x 768)
    split_kernel<0><<<blks(BQ_ROWS * D_), T>>>(opp, op2, BQ_ROWS);
    gemm_mma<<<dim3(D_ / 128, BQ_ROWS / 128), T, SMEM>>>(op2, Wout2, out, BQ_ROWS, D_);
}